// round 16
// baseline (speedup 1.0000x reference)
#include <cuda_runtime.h>
#include <cstdint>

// ConvTranspose2d(64->64,k4,s2,p1)+bias+mish+(+0.5,clip,*2) via mma.sync fp16 (f32 accum).
// y[p,oc] = sum_k A[p,k]*B[oc,k], k = (b*2+a)*64 + ic, K=256.
//   pixel p=(ohi,m): oh = ph+4*tglob+2*ohi, ow = 2m+pw ; Rb = 2*tglob+ph
//   A[p,k] = x[n, ic, Rb+ohi-a, m+pw-b]  (zero OOB), B[oc,k]=w[oc,ic,(1-ph)+2a,(1-pw)+2b]
// == Round-11 (best: 192.5us) with ONE change: the 16 k16-steps are software-
// pipelined with explicit ping-pong fragment buffers (load step q+1's 4 ldsm
// before step q's 8 mma) so the HMMA pipe stays fed through the ldsm latency
// windows even when barriers phase-align the 4 warps per SMSP.
// 5-slot fp16 row ring (row=slot*64+j, 128B = 64 ic, 16B-chunk swizzle ^(j&7)<<4,
// OOB j -> ZROW). Staging: LDG.32 ic-pair -> cvt.rn.f16x2 -> STS.32.
// Work unit = 4 tiles (512 units/ph, 74 slots). Grid 148, 512 thr,
// 16 warps = (pw, och, mq), warp tile 32px x 32oc.
// Epilogue: dedicated 2x16KB ys, 4 chunks x 16oc, store(q) overlaps write(q+1).

#define NT 512
#define SM_B    256
#define SM_RING (SM_B + 65536)             // 65792
#define ZROW    320
#define SM_YS   (SM_RING + 321 * 128)      // 106880
#define SMEM_TOTAL (SM_YS + 32768)         // 139648

static __device__ __forceinline__ uint32_t s2u(const void* p) {
    uint32_t a;
    asm("{ .reg .u64 t; cvta.to.shared.u64 t, %1; cvt.u32.u64 %0, t; }" : "=r"(a) : "l"(p));
    return a;
}
static __device__ __forceinline__ uint32_t f2h2(float lo, float hi) {
    uint32_t r;
    asm("cvt.rn.f16x2.f32 %0, %1, %2;" : "=r"(r) : "f"(hi), "f"(lo));
    return r;
}
static __device__ __forceinline__ void sts32(uint32_t addr, uint32_t v) {
    asm volatile("st.shared.b32 [%0], %1;" :: "r"(addr), "r"(v) : "memory");
}
static __device__ __forceinline__ void ldsm4(uint32_t* r, uint32_t addr) {
    asm volatile("ldmatrix.sync.aligned.m8n8.x4.shared.b16 {%0,%1,%2,%3}, [%4];"
                 : "=r"(r[0]), "=r"(r[1]), "=r"(r[2]), "=r"(r[3]) : "r"(addr));
}
static __device__ __forceinline__ void mma16(float* d, const uint32_t* a,
                                             uint32_t b0, uint32_t b1) {
    asm volatile("mma.sync.aligned.m16n8k16.row.col.f32.f16.f16.f32 "
                 "{%0,%1,%2,%3}, {%4,%5,%6,%7}, {%8,%9}, {%0,%1,%2,%3};"
                 : "+f"(d[0]), "+f"(d[1]), "+f"(d[2]), "+f"(d[3])
                 : "r"(a[0]), "r"(a[1]), "r"(a[2]), "r"(a[3]), "r"(b0), "r"(b1));
}
__device__ __forceinline__ float postop(float y) {
    // mish(y) = y*(t^2+2t)/(t^2+2t+2), t=e^y ; then +0.5, clip[-1,1], *2
    float t = __expf(fminf(y, 30.0f));
    float u = t * (t + 2.0f);
    float mish = y * __fdividef(u, u + 2.0f);
    float v = fminf(fmaxf(mish + 0.5f, -1.0f), 1.0f);
    return v * 2.0f;
}
// ys: 32 rows x 512B, 16B-chunk XOR swizzle by (row&31)
static __device__ __forceinline__ uint32_t ysaddr(uint32_t base, int row, int p) {
    return base + (uint32_t)row * 512 + ((((uint32_t)p >> 2) ^ (uint32_t)(row & 31)) << 4)
         + (((uint32_t)p & 3) << 2);
}

// stage nrows rows starting at rg0: LDG.32 ic-pair -> f16x2 -> STS.32
static __device__ __forceinline__ void stage_rows(const float* xn, int rg0, int nrows,
                                                  uint32_t sb, int tid) {
    const int total = nrows * 2048;        // pairs: 32 icp x 64 j per row
#pragma unroll 4
    for (int idx = tid; idx < total; idx += NT) {
        int j   = idx & 63;
        int icp = (idx >> 6) & 31;
        int rr  = idx >> 11;
        int rg  = rg0 + rr;
        float v0 = 0.0f, v1 = 0.0f;
        if ((unsigned)rg < 64u) {
            const float* p0 = xn + ((2 * icp) * 64 + rg) * 64 + j;
            v0 = __ldg(p0);
            v1 = __ldg(p0 + 4096);
        }
        int row = ((rg + 5) % 5) * 64 + j;
        uint32_t dst = sb + SM_RING + row * 128
                     + (((uint32_t)icp << 2) ^ (((uint32_t)j & 7) << 4));
        sts32(dst, f2h2(v0, v1));
    }
}

__global__ __launch_bounds__(NT, 1)
void convt_mma_kernel(const float* __restrict__ x,
                      const float* __restrict__ weight,
                      const float* __restrict__ bias,
                      float* __restrict__ out) {
    extern __shared__ char smem[];
    const uint32_t sb = s2u(smem);
    const int tid  = threadIdx.x;
    const int warp = tid >> 5;
    const int lane = tid & 31;
    const int ph   = blockIdx.x & 1;
    const int slot = blockIdx.x >> 1;      // 0..73

    if (tid < 64) ((float*)smem)[tid] = bias[tid];

    // ---- stage B once (fp16): row = pw*64+oc (512B), word kp: byte = kp*4 ^ ((oc&7)<<4) ----
    for (int it = 0; it < 32; it++) {
        int idx = tid + it * NT;           // 0..16383 (k-pairs)
        int kp = idx & 127;                // k0 = 2*kp
        int oc = (idx >> 7) & 63;
        int pw = idx >> 13;
        int k0 = 2 * kp;
        int g = k0 >> 6, ic = k0 & 63, a = g & 1, b = g >> 1;
        int kh = (1 - ph) + 2 * a;
        int kw = (1 - pw) + 2 * b;
        const float* wp = weight + ((oc * 64 + ic) << 4) + (kh << 2) + kw;
        float f0 = __ldg(wp);
        float f1 = __ldg(wp + 16);         // ic+1, same (kh,kw)
        uint32_t byte = ((uint32_t)(kp << 2)) ^ ((uint32_t)(oc & 7) << 4);
        sts32(sb + SM_B + (pw * 64 + oc) * 512 + byte, f2h2(f0, f1));
    }
    if (tid < 32) sts32(sb + SM_RING + ZROW * 128 + tid * 4, 0u);   // zero row

    // warp roles: pw | och | mq
    const int pw  = warp >> 3;
    const int och = (warp >> 2) & 1;
    const int mq  = warp & 3;
    const int p0  = 32 * mq;
    const int ohi = mq >> 1;
    const int msub0 = 32 * (mq & 1);

    const int l15 = lane & 15;
    const int lhi = lane >> 4;
    const int oc_l = (lane & 7) + 8 * lhi;
    const uint32_t khalf = (uint32_t)((lane >> 3) & 1) << 4;
    const uint32_t swzB  = (uint32_t)(lane & 7) << 4;
    uint32_t rbB[2];
#pragma unroll
    for (int jp = 0; jp < 2; jp++)
        rbB[jp] = sb + SM_B + (uint32_t)(pw * 64 + 32 * och + 16 * jp + oc_l) * 512;

    const int gL = lane >> 2, tg = lane & 3;
    const float* bsm = (const float*)smem;

    for (int u = slot; u < 512; u += 74) {
        const int n  = u >> 3;
        const int uh = u & 7;
        const int Rb0 = 8 * uh + ph;
        const float* xn = x + (size_t)n * (64 * 64 * 64);

        // ---- prologue: rows Rb0-1..Rb0+1 ----
        stage_rows(xn, Rb0 - 1, 3, sb, tid);
        __syncthreads();

        for (int tl = 0; tl < 4; tl++) {
            const int Rb = Rb0 + 2 * tl;
            const int tglob = 4 * uh + tl;

            // ---- phase A: stage rows Rb+2, Rb+3 (next tile) ----
            if (tl < 3) stage_rows(xn, Rb + 2, 2, sb, tid);

            // ---- phase B: software-pipelined 16 k16-steps ----
            float acc[2][4][4];
#pragma unroll
            for (int i = 0; i < 2; i++)
#pragma unroll
                for (int j = 0; j < 4; j++)
#pragma unroll
                    for (int e = 0; e < 4; e++) acc[i][j][e] = 0.0f;

            // per-g A-base tables
            uint32_t gb0[4], gb1[4], gr0[4], gr1[4];
#pragma unroll
            for (int g = 0; g < 4; g++) {
                const int a = g & 1, b = g >> 1;
                const int rgA = Rb + ohi - a;
                const int slotA = (rgA + 5) % 5;
                const int jA = msub0 + pw - b + l15;
                const int rowL0 = ((unsigned)jA < 64u) ? slotA * 64 + jA : ZROW;
                const int rowL1 = ((unsigned)(jA + 16) < 64u) ? slotA * 64 + jA + 16 : ZROW;
                gb0[g] = sb + SM_RING + (uint32_t)rowL0 * 128;
                gb1[g] = sb + SM_RING + (uint32_t)rowL1 * 128;
                gr0[g] = (uint32_t)(rowL0 & 7);
                gr1[g] = (uint32_t)(rowL1 & 7);
            }

            // ping-pong fragment buffers: [0:4)=Af0 [4:8)=Af1 [8:12)=Bf0 [12:16)=Bf1
            uint32_t FR[2][16];
#define LOAD_FRAGS(q, F) do {                                                 \
    const int g_ = (q) >> 2;                                                  \
    const uint32_t ch_ = (uint32_t)(((q) & 3) << 1) + (uint32_t)lhi;          \
    const uint32_t kb_ = (((uint32_t)(q) << 5) + khalf) ^ swzB;               \
    ldsm4((F) + 0,  gb0[g_] + ((ch_ ^ gr0[g_]) << 4));                        \
    ldsm4((F) + 4,  gb1[g_] + ((ch_ ^ gr1[g_]) << 4));                        \
    ldsm4((F) + 8,  rbB[0] + kb_);                                            \
    ldsm4((F) + 12, rbB[1] + kb_);                                            \
} while (0)

            LOAD_FRAGS(0, FR[0]);
#pragma unroll
            for (int q = 0; q < 16; q++) {
                if (q < 15) LOAD_FRAGS(q + 1, FR[(q + 1) & 1]);
                const uint32_t* F = FR[q & 1];
                mma16(acc[0][0], F + 0, F[8],  F[9]);
                mma16(acc[0][1], F + 0, F[10], F[11]);
                mma16(acc[0][2], F + 0, F[12], F[13]);
                mma16(acc[0][3], F + 0, F[14], F[15]);
                mma16(acc[1][0], F + 4, F[8],  F[9]);
                mma16(acc[1][1], F + 4, F[10], F[11]);
                mma16(acc[1][2], F + 4, F[12], F[13]);
                mma16(acc[1][3], F + 4, F[14], F[15]);
            }
#undef LOAD_FRAGS
            __syncthreads();   // sync1: ring reads done; phase-A STS visible next tile

            // ---- phase C: ys double-buffer (dedicated), 4 chunks x 16oc ----
            const uint32_t ysA = sb + SM_YS;
            const uint32_t ysB = sb + SM_YS + 16384;
            const int rowc = pw * 16 + 8 * och + 2 * tg;

#define WRITE_CHUNK(q, base) do {                                            \
    const int occ_ = 32 * och + 8 * (q) + 2 * tg;                            \
    const float b0v_ = bsm[occ_], b1v_ = bsm[occ_ + 1];                      \
    _Pragma("unroll")                                                        \
    for (int i_ = 0; i_ < 2; i_++) {                                         \
        const int pr_ = p0 + 16 * i_ + gL;                                   \
        sts32(ysaddr((base), rowc,     pr_),     __float_as_uint(postop(acc[i_][q][0] + b0v_))); \
        sts32(ysaddr((base), rowc + 1, pr_),     __float_as_uint(postop(acc[i_][q][1] + b1v_))); \
        sts32(ysaddr((base), rowc,     pr_ + 8), __float_as_uint(postop(acc[i_][q][2] + b0v_))); \
        sts32(ysaddr((base), rowc + 1, pr_ + 8), __float_as_uint(postop(acc[i_][q][3] + b1v_))); \
    } } while (0)

#define STORE_CHUNK(q, base) do {                                            \
    const char* yb_ = smem + ((base) - sb);                                  \
    _Pragma("unroll")                                                        \
    for (int it_ = 0; it_ < 2; it_++) {                                      \
        int vid_ = tid + it_ * NT;                                           \
        int ow4_ = vid_ & 31;                                                \
        int rw_  = vid_ >> 5;                                                \
        int oh2_ = rw_ & 1;                                                  \
        int ocx_ = rw_ >> 1;                                                 \
        int oc_  = 32 * (ocx_ >> 3) + 8 * (q) + (ocx_ & 7);                  \
        int p_   = oh2_ * 64 + 2 * ow4_;                                     \
        float4 v_;                                                           \
        v_.x = *(const float*)(yb_ + (ysaddr(0u, ocx_,      p_)));           \
        v_.y = *(const float*)(yb_ + (ysaddr(0u, 16 + ocx_, p_)));           \
        v_.z = *(const float*)(yb_ + (ysaddr(0u, ocx_,      p_ + 1)));       \
        v_.w = *(const float*)(yb_ + (ysaddr(0u, 16 + ocx_, p_ + 1)));       \
        int oh_ = ph + 4 * tglob + 2 * oh2_;                                 \
        *(float4*)(out + (((size_t)n * 64 + oc_) * 128 + oh_) * 128 + 4 * ow4_) = v_; \
    } } while (0)

            WRITE_CHUNK(0, ysA);
            __syncthreads();
            STORE_CHUNK(0, ysA); WRITE_CHUNK(1, ysB);
            __syncthreads();
            STORE_CHUNK(1, ysB); WRITE_CHUNK(2, ysA);
            __syncthreads();
            STORE_CHUNK(2, ysA); WRITE_CHUNK(3, ysB);
            __syncthreads();
            STORE_CHUNK(3, ysB);
            __syncthreads();
#undef WRITE_CHUNK
#undef STORE_CHUNK
        }
    }
}

extern "C" void kernel_launch(void* const* d_in, const int* in_sizes, int n_in,
                              void* d_out, int out_size) {
    const float* x      = (const float*)d_in[0];
    const float* weight = (const float*)d_in[1];
    const float* bias   = (const float*)d_in[2];
    float* out          = (float*)d_out;

    cudaFuncSetAttribute(convt_mma_kernel,
                         cudaFuncAttributeMaxDynamicSharedMemorySize, SMEM_TOTAL);
    convt_mma_kernel<<<148, NT, SMEM_TOTAL>>>(x, weight, bias, out);
}